// round 16
// baseline (speedup 1.0000x reference)
#include <cuda_runtime.h>
#include <cuda_fp16.h>
#include <cstdint>

#define INSIZE 512
#define NREFL  64
#define BATCH  8192

// ---------------- device scratch ----------------
__device__ float  g_sigma[INSIZE];
__device__ float  g_gram[2][64][64];
__device__ float  g_T[2][64][64];       // T[row][col], app order
__device__ float  g_XG[64 * 64];        // XG[k][b] = sum_j U[k][j]*sig[j]*V[63-b][j]
__device__ __half g_MT[512 * 512];      // M^T fp16

// ---------------- helpers ----------------
__device__ __forceinline__ uint32_t smem_u32(const void* p) {
    uint32_t a;
    asm("{ .reg .u64 t; cvta.to.shared.u64 t, %1; cvt.u32.u64 %0, t; }" : "=r"(a) : "l"(p));
    return a;
}
__device__ __forceinline__ void cp_async16(uint32_t dst, const void* src) {
    asm volatile("cp.async.cg.shared.global [%0], [%1], 16;" :: "r"(dst), "l"(src) : "memory");
}
#define CP_COMMIT() asm volatile("cp.async.commit_group;" ::: "memory")
#define CP_WAIT1()  asm volatile("cp.async.wait_group 1;" ::: "memory")
#define SWZ64(o) ((o) ^ (((o) >> 3) & 0x30))

__device__ __forceinline__ void ldsm_x4(uint32_t* r, uint32_t addr) {
    asm volatile("ldmatrix.sync.aligned.m8n8.x4.shared.b16 {%0,%1,%2,%3}, [%4];"
                 : "=r"(r[0]), "=r"(r[1]), "=r"(r[2]), "=r"(r[3]) : "r"(addr));
}
__device__ __forceinline__ void mma16816(float* d, const uint32_t* a, const uint32_t* b) {
    asm volatile("mma.sync.aligned.m16n8k16.row.col.f32.f16.f16.f32 "
                 "{%0,%1,%2,%3}, {%4,%5,%6,%7}, {%8,%9}, {%0,%1,%2,%3};"
                 : "+f"(d[0]), "+f"(d[1]), "+f"(d[2]), "+f"(d[3])
                 : "r"(a[0]), "r"(a[1]), "r"(a[2]), "r"(a[3]), "r"(b[0]), "r"(b[1]));
}
__device__ __forceinline__ float sigmoid_sig(float v) {
    return 0.1f + 0.9f * (1.0f / (1.0f + expf(-v)));
}
__device__ __forceinline__ float dot4(float4 a, float4 b) {
    return a.x * b.x + a.y * b.y + a.z * b.z + a.w * b.w;
}

// ---------------------------------------------------------------------------
// K1: grams (1024 blocks) | XG (512 blocks). sigma -> global (block 0).
// ---------------------------------------------------------------------------
__global__ __launch_bounds__(256)
void k1_kernel(const float* __restrict__ p,
               const float* __restrict__ U, const float* __restrict__ V)
{
    const int b = blockIdx.x, t = threadIdx.x;
    if (b < 1024) {
        if (b == 0) {
            g_sigma[t]       = sigmoid_sig(p[t]);
            g_sigma[t + 256] = sigmoid_sig(p[t + 256]);
        }
        const int task = b * 8 + (t >> 5);
        const int lane = t & 31;
        const int mat = task >> 12;
        const int e = task & 4095;
        const int a = e >> 6, c = e & 63;
        const float* M = mat ? V : U;
        const float4* ra = (const float4*)(M + (size_t)a * 512);
        const float4* rb = (const float4*)(M + (size_t)c * 512);
        float ss = 0.f;
        #pragma unroll
        for (int j = lane; j < 128; j += 32)
            ss += dot4(__ldg(&ra[j]), __ldg(&rb[j]));
        #pragma unroll
        for (int o = 16; o > 0; o >>= 1) ss += __shfl_xor_sync(0xffffffffu, ss, o);
        if (lane == 0) g_gram[mat][a][c] = ss;
    } else {
        __shared__ float ssig[512];
        ssig[t]       = sigmoid_sig(p[t]);
        ssig[t + 256] = sigmoid_sig(p[t + 256]);
        __syncthreads();
        const int task = (b - 1024) * 8 + (t >> 5);
        const int lane = t & 31;
        const int k = task >> 6, bb = task & 63;
        const float4* ru = (const float4*)(U + (size_t)k * 512);
        const float4* rv = (const float4*)(V + (size_t)(63 - bb) * 512);
        const float4* sg = (const float4*)ssig;
        float ss = 0.f;
        #pragma unroll
        for (int j = lane; j < 128; j += 32) {
            float4 a4 = __ldg(&ru[j]), b4 = __ldg(&rv[j]), s4 = sg[j];
            ss += a4.x * s4.x * b4.x + a4.y * s4.y * b4.y
                + a4.z * s4.z * b4.z + a4.w * s4.w * b4.w;
        }
        #pragma unroll
        for (int o = 16; o > 0; o >>= 1) ss += __shfl_xor_sync(0xffffffffu, ss, o);
        if (lane == 0) g_XG[k * 64 + bb] = ss;
    }
}

// ---------------------------------------------------------------------------
// tinv (proven): T = inv(D^-1 + strict_upper(Gram)). 4 blocks.
// ---------------------------------------------------------------------------
__global__ __launch_bounds__(1024)
void tinv_kernel()
{
    __shared__ float Gs[2][64][64];
    const int t = threadIdx.x;
    for (int i = t; i < 2 * 4096; i += 1024)
        ((float*)Gs)[i] = ((const float*)g_gram)[i];
    __syncthreads();

    const int w = t >> 5, lane = t & 31;
    const int task = w + 32 * blockIdx.x;
    const int mat = task >> 6, c = task & 63;
    auto Lv = [&](int a, int m) -> float {
        if (mat == 0) return (a == m) ? Gs[0][a][a] * 0.5f : Gs[0][a][m];
        return (a == m) ? Gs[1][63 - a][63 - a] * 0.5f : Gs[1][63 - a][63 - m];
    };
    float t0 = 0.f, t1 = 0.f;
    {
        const float inv = 1.0f / Lv(c, c);
        if (lane == c) t0 = inv;
        if (lane + 32 == c) t1 = inv;
    }
    for (int a = c - 1; a >= 0; --a) {
        float s = 0.f;
        if (lane > a && lane <= c)            s += Lv(a, lane) * t0;
        if (lane + 32 > a && lane + 32 <= c)  s += Lv(a, lane + 32) * t1;
        #pragma unroll
        for (int o = 16; o > 0; o >>= 1) s += __shfl_xor_sync(0xffffffffu, s, o);
        const float ta = -s / Lv(a, a);
        if (lane == a) t0 = ta;
        if (lane + 32 == a) t1 = ta;
    }
    g_T[mat][lane][c]      = t0;
    g_T[mat][lane + 32][c] = t1;
}

// ---------------------------------------------------------------------------
// fusedM (R15-proven): block per 64x64 tile of M; all small mms local.
// ---------------------------------------------------------------------------
#define FM_SMEM ((7 * 4096 + 128) * 4)

__global__ __launch_bounds__(256)
void fusedM_kernel(const float* __restrict__ U, const float* __restrict__ V)
{
    extern __shared__ __align__(16) float dyn[];
    float* R0 = dyn;               // TuT[k][a]  -> Ul[a][di]
    float* R1 = dyn + 4096;        // XG[k][b]   -> TvT[k][b] -> Vl[b][di]
    float* R2 = dyn + 8192;        // C2[a][b]
    float* R3 = dyn + 12288;       // W-slice staging [k][dj]
    float* R4 = dyn + 16384;       // C1s[a][dj]
    float* R5 = dyn + 20480;       // Ws[b][dj]
    float* R6 = dyn + 24576;       // E[b][di]
    float* sgi = dyn + 28672;
    float* sgj = sgi + 64;

    const int t = threadIdx.x;
    const int ti = t & 15, tj = t >> 4;
    const int i0 = (blockIdx.x & 7) * 64, j0 = (blockIdx.x >> 3) * 64;

    for (int idx = t; idx < 4096; idx += 256)
        R0[(idx & 63) * 64 + (idx >> 6)] = (&g_T[0][0][0])[idx];
    for (int idx = t; idx < 1024; idx += 256)
        ((float4*)R1)[idx] = ((const float4*)g_XG)[idx];
    if (t < 64)        sgi[t] = g_sigma[i0 + t];
    else if (t < 128)  sgj[t - 64] = g_sigma[j0 + (t - 64)];
    __syncthreads();

    float acc[4][4];
    #define ZERO_ACC() { _Pragma("unroll") for (int r = 0; r < 4; ++r) \
                         _Pragma("unroll") for (int c = 0; c < 4; ++c) acc[r][c] = 0.f; }
    #define MM_STEP(Abuf, Bbuf, k) { \
        float4 av = *(const float4*)&(Abuf)[(k) * 64 + ti * 4]; \
        float4 bv = *(const float4*)&(Bbuf)[(k) * 64 + tj * 4]; \
        const float aa[4] = { av.x, av.y, av.z, av.w }; \
        const float bb[4] = { bv.x, bv.y, bv.z, bv.w }; \
        _Pragma("unroll") for (int r = 0; r < 4; ++r) \
        _Pragma("unroll") for (int c = 0; c < 4; ++c) acc[r][c] += aa[r] * bb[c]; }

    // C2 = TuT^T * XG
    ZERO_ACC();
    #pragma unroll 4
    for (int k = 0; k < 64; ++k) MM_STEP(R0, R1, k);
    #pragma unroll
    for (int r = 0; r < 4; ++r)
        *(float4*)&R2[(ti * 4 + r) * 64 + tj * 4]
            = make_float4(acc[r][0], acc[r][1], acc[r][2], acc[r][3]);
    __syncthreads();

    // C1s
    for (int idx = t; idx < 1024; idx += 256) {
        const int row = idx >> 4, c4 = idx & 15;
        *(float4*)&R3[row * 64 + c4 * 4]
            = __ldg((const float4*)&U[(size_t)row * 512 + j0 + c4 * 4]);
    }
    __syncthreads();
    ZERO_ACC();
    #pragma unroll 4
    for (int k = 0; k < 64; ++k) MM_STEP(R0, R3, k);
    {
        const float s0 = sgj[tj * 4], s1 = sgj[tj * 4 + 1];
        const float s2 = sgj[tj * 4 + 2], s3 = sgj[tj * 4 + 3];
        #pragma unroll
        for (int r = 0; r < 4; ++r)
            *(float4*)&R4[(ti * 4 + r) * 64 + tj * 4]
                = make_float4(acc[r][0] * s0, acc[r][1] * s1, acc[r][2] * s2, acc[r][3] * s3);
    }
    __syncthreads();

    // Ws
    for (int idx = t; idx < 4096; idx += 256)
        R1[(idx & 63) * 64 + (idx >> 6)] = (&g_T[1][0][0])[idx];
    for (int idx = t; idx < 1024; idx += 256) {
        const int row = idx >> 4, c4 = idx & 15;
        *(float4*)&R3[row * 64 + c4 * 4]
            = __ldg((const float4*)&V[(size_t)(63 - row) * 512 + j0 + c4 * 4]);
    }
    __syncthreads();
    ZERO_ACC();
    #pragma unroll 4
    for (int k = 0; k < 64; ++k) MM_STEP(R1, R3, k);
    #pragma unroll
    for (int r = 0; r < 4; ++r)
        *(float4*)&R5[(ti * 4 + r) * 64 + tj * 4]
            = make_float4(acc[r][0], acc[r][1], acc[r][2], acc[r][3]);
    __syncthreads();

    // Ul, Vl
    for (int idx = t; idx < 1024; idx += 256) {
        const int row = idx >> 4, c4 = idx & 15;
        *(float4*)&R0[row * 64 + c4 * 4]
            = __ldg((const float4*)&U[(size_t)row * 512 + i0 + c4 * 4]);
        *(float4*)&R1[row * 64 + c4 * 4]
            = __ldg((const float4*)&V[(size_t)(63 - row) * 512 + i0 + c4 * 4]);
    }
    __syncthreads();

    // E
    ZERO_ACC();
    #pragma unroll 4
    for (int a = 0; a < 64; ++a) MM_STEP(R0, R2, a);
    {
        const float s0 = sgi[ti * 4], s1 = sgi[ti * 4 + 1];
        const float s2 = sgi[ti * 4 + 2], s3 = sgi[ti * 4 + 3];
        #pragma unroll
        for (int c = 0; c < 4; ++c) {
            const int b = tj * 4 + c;
            float4 vl = *(const float4*)&R1[b * 64 + ti * 4];
            *(float4*)&R6[b * 64 + ti * 4]
                = make_float4(s0 * vl.x - acc[0][c], s1 * vl.y - acc[1][c],
                              s2 * vl.z - acc[2][c], s3 * vl.w - acc[3][c]);
        }
    }
    __syncthreads();

    // M
    ZERO_ACC();
    #pragma unroll 4
    for (int a = 0; a < 64; ++a) MM_STEP(R0, R4, a);
    #pragma unroll 4
    for (int b = 0; b < 64; ++b) MM_STEP(R6, R5, b);
    #pragma unroll
    for (int c = 0; c < 4; ++c) {
        const int j = j0 + tj * 4 + c;
        float m[4];
        #pragma unroll
        for (int r = 0; r < 4; ++r) {
            const int i = i0 + ti * 4 + r;
            m[r] = -acc[r][c] + (i == j ? sgi[ti * 4 + r] : 0.f);
        }
        __half* dst = &g_MT[(size_t)j * 512 + i0 + ti * 4];
        *(__half2*)(dst)     = __floats2half2_rn(m[0], m[1]);
        *(__half2*)(dst + 2) = __floats2half2_rn(m[2], m[3]);
    }
}

// ---------------------------------------------------------------------------
// GEMM with in-kernel A conversion: out = fp16(x) * M + bias.
// smem: 3 x (8KB Afp16 + 8KB B) + 2 x 16KB fp32 A scratch = 80KB dynamic.
// ---------------------------------------------------------------------------
#define TM 128
#define TN 128
#define NKS 16
#define STG 16384
#define SCR_OFF (3 * STG)            // 49152
#define GEMM_SMEM (SCR_OFF + 2 * 16384)   // 81920

__global__ __launch_bounds__(256, 2)
void gemm_kernel(const float* __restrict__ x, float* __restrict__ out,
                 const float* __restrict__ bias)
{
    extern __shared__ __align__(1024) char sm[];
    const uint32_t sbase = smem_u32(sm);
    const int t = threadIdx.x;
    const int lane = t & 31, wid = t >> 5;
    const int wm = wid & 3, wn = wid >> 2;
    const int m0 = blockIdx.x * TM, n0 = blockIdx.y * TN;
    const int arow = t >> 1, ahalf = t & 1;        // A-convert mapping

    float acc[2][8][4];
    #pragma unroll
    for (int fm = 0; fm < 2; ++fm)
        #pragma unroll
        for (int fn = 0; fn < 8; ++fn)
            #pragma unroll
            for (int j = 0; j < 4; ++j) acc[fm][fn][j] = 0.f;

    // issue cp.async for stage ks: fp32 A -> scratch[ks&1], fp16 B -> slot ks%3
    auto load_stage = [&](int ks) {
        const uint32_t scr = sbase + SCR_OFF + (uint32_t)(ks & 1) * 16384
                           + (uint32_t)(arow * 128 + ahalf * 64);
        const float* src = x + (size_t)(m0 + arow) * 512 + ks * 32 + ahalf * 16;
        #pragma unroll
        for (int q = 0; q < 4; ++q)
            cp_async16(scr + q * 16, src + q * 4);
        const __half* Bb = (const __half*)g_MT + (size_t)n0 * 512 + ks * 32;
        const uint32_t sB = sbase + (uint32_t)(ks % 3) * STG + 8192;
        #pragma unroll
        for (int i = 0; i < 2; ++i) {
            const int idx = t + i * 256;
            const int row = idx >> 2, c = idx & 3;
            cp_async16(sB + SWZ64((uint32_t)(row * 64 + c * 16)),
                       Bb + (size_t)row * 512 + c * 8);
        }
    };

    // convert scratch[ks&1] fp32 -> Aslot[ks%3] fp16 (swizzled)
    auto convert_stage = [&](int ks) {
        const char* scr = sm + SCR_OFF + (ks & 1) * 16384 + arow * 128 + ahalf * 64;
        float4 f0 = *(const float4*)(scr);
        float4 f1 = *(const float4*)(scr + 16);
        float4 f2 = *(const float4*)(scr + 32);
        float4 f3 = *(const float4*)(scr + 48);
        __align__(16) __half2 hv[8];
        hv[0] = __floats2half2_rn(f0.x, f0.y); hv[1] = __floats2half2_rn(f0.z, f0.w);
        hv[2] = __floats2half2_rn(f1.x, f1.y); hv[3] = __floats2half2_rn(f1.z, f1.w);
        hv[4] = __floats2half2_rn(f2.x, f2.y); hv[5] = __floats2half2_rn(f2.z, f2.w);
        hv[6] = __floats2half2_rn(f3.x, f3.y); hv[7] = __floats2half2_rn(f3.z, f3.w);
        char* dstbase = sm + (ks % 3) * STG;
        const uint32_t o0 = SWZ64((uint32_t)(arow * 64 + ahalf * 32));
        const uint32_t o1 = SWZ64((uint32_t)(arow * 64 + ahalf * 32 + 16));
        *(uint4*)(dstbase + o0) = *(const uint4*)&hv[0];
        *(uint4*)(dstbase + o1) = *(const uint4*)&hv[4];
    };

    auto compute_stage = [&](int st) {
        const uint32_t sA = sbase + st * STG;
        const uint32_t sB = sA + 8192;
        #pragma unroll
        for (int kf = 0; kf < 2; ++kf) {
            uint32_t a[2][4], b[4][4];
            #pragma unroll
            for (int fm = 0; fm < 2; ++fm) {
                const int row = wm * 32 + fm * 16 + (lane & 15);
                const int c   = kf * 2 + (lane >> 4);
                ldsm_x4(a[fm], sA + SWZ64((uint32_t)(row * 64 + c * 16)));
            }
            #pragma unroll
            for (int fp = 0; fp < 4; ++fp) {
                const int row = wn * 64 + fp * 16 + ((lane >> 4) << 3) + (lane & 7);
                const int c   = kf * 2 + ((lane >> 3) & 1);
                ldsm_x4(b[fp], sB + SWZ64((uint32_t)(row * 64 + c * 16)));
            }
            #pragma unroll
            for (int fm = 0; fm < 2; ++fm)
                #pragma unroll
                for (int fn = 0; fn < 8; ++fn)
                    mma16816(acc[fm][fn], a[fm], &b[fn >> 1][(fn & 1) * 2]);
        }
    };

    load_stage(0); CP_COMMIT();
    load_stage(1); CP_COMMIT();

    #pragma unroll 1
    for (int ks = 0; ks < NKS; ++ks) {
        CP_WAIT1();                     // A fp32(ks) + B(ks) resident
        __syncthreads();
        convert_stage(ks);              // scratch[ks&1] -> Aslot[ks%3]
        __syncthreads();                // Afp16 visible; scratch[ks&1] free
        if (ks + 2 < NKS) load_stage(ks + 2);
        CP_COMMIT();
        compute_stage(ks % 3);
    }

    #pragma unroll
    for (int fm = 0; fm < 2; ++fm) {
        const int r = m0 + wm * 32 + fm * 16 + (lane >> 2);
        #pragma unroll
        for (int fn = 0; fn < 8; ++fn) {
            const int cb = n0 + wn * 64 + fn * 8 + (lane & 3) * 2;
            const float2 bi = __ldg((const float2*)(bias + cb));
            float2 v0, v1;
            v0.x = acc[fm][fn][0] + bi.x; v0.y = acc[fm][fn][1] + bi.y;
            v1.x = acc[fm][fn][2] + bi.x; v1.y = acc[fm][fn][3] + bi.y;
            *(float2*)(out + (size_t)r * 512 + cb)       = v0;
            *(float2*)(out + (size_t)(r + 8) * 512 + cb) = v1;
        }
    }
}

// ---------------------------------------------------------------------------
extern "C" void kernel_launch(void* const* d_in, const int* in_sizes, int n_in,
                              void* d_out, int out_size)
{
    (void)in_sizes; (void)n_in; (void)out_size;
    const float* x    = (const float*)d_in[0];
    const float* p    = (const float*)d_in[1];
    const float* U    = (const float*)d_in[2];
    const float* V    = (const float*)d_in[3];
    const float* bias = (const float*)d_in[4];

    cudaFuncSetAttribute(fusedM_kernel, cudaFuncAttributeMaxDynamicSharedMemorySize,
                         FM_SMEM);
    cudaFuncSetAttribute(gemm_kernel, cudaFuncAttributeMaxDynamicSharedMemorySize,
                         GEMM_SMEM);

    k1_kernel<<<1536, 256>>>(p, U, V);
    tinv_kernel<<<4, 1024>>>();
    fusedM_kernel<<<64, 256, FM_SMEM>>>(U, V);
    gemm_kernel<<<dim3(BATCH / TM, 512 / TN), 256, GEMM_SMEM>>>(x, (float*)d_out, bias);
}

// round 17
// speedup vs baseline: 1.1531x; 1.1531x over previous
#include <cuda_runtime.h>
#include <cuda_fp16.h>
#include <cstdint>

#define INSIZE 512
#define NREFL  64
#define BATCH  8192

// ---------------- device scratch ----------------
__device__ float  g_sigma[INSIZE];
__device__ float  g_gram[2][64][64];
__device__ float  g_T[2][64][64];       // T[row][col], app order
__device__ float  g_XG[64 * 64];        // XG[k][b] = sum_j U[k][j]*sig[j]*V[63-b][j]
__device__ __half g_MT[512 * 512];      // M^T fp16
__device__ __half g_xh[BATCH * INSIZE]; // x fp16

// ---------------- helpers ----------------
__device__ __forceinline__ uint32_t smem_u32(const void* p) {
    uint32_t a;
    asm("{ .reg .u64 t; cvta.to.shared.u64 t, %1; cvt.u32.u64 %0, t; }" : "=r"(a) : "l"(p));
    return a;
}
__device__ __forceinline__ void cp_async16(uint32_t dst, const void* src) {
    asm volatile("cp.async.cg.shared.global [%0], [%1], 16;" :: "r"(dst), "l"(src) : "memory");
}
#define CP_COMMIT() asm volatile("cp.async.commit_group;" ::: "memory")
#define CP_WAIT1()  asm volatile("cp.async.wait_group 1;" ::: "memory")
#define SWZ64(o)  ((o) ^ (((o) >> 3) & 0x30))
#define SWZ128(o) ((o) ^ (((o) >> 3) & 0x70))

__device__ __forceinline__ void ldsm_x4(uint32_t* r, uint32_t addr) {
    asm volatile("ldmatrix.sync.aligned.m8n8.x4.shared.b16 {%0,%1,%2,%3}, [%4];"
                 : "=r"(r[0]), "=r"(r[1]), "=r"(r[2]), "=r"(r[3]) : "r"(addr));
}
__device__ __forceinline__ void mma16816(float* d, const uint32_t* a, const uint32_t* b) {
    asm volatile("mma.sync.aligned.m16n8k16.row.col.f32.f16.f16.f32 "
                 "{%0,%1,%2,%3}, {%4,%5,%6,%7}, {%8,%9}, {%0,%1,%2,%3};"
                 : "+f"(d[0]), "+f"(d[1]), "+f"(d[2]), "+f"(d[3])
                 : "r"(a[0]), "r"(a[1]), "r"(a[2]), "r"(a[3]), "r"(b[0]), "r"(b[1]));
}
__device__ __forceinline__ float sigmoid_sig(float v) {
    return 0.1f + 0.9f * (1.0f / (1.0f + expf(-v)));
}
__device__ __forceinline__ float dot4(float4 a, float4 b) {
    return a.x * b.x + a.y * b.y + a.z * b.z + a.w * b.w;
}

// ---------------------------------------------------------------------------
// K1 (R15-proven): conv x->fp16 | grams | XG. sigma -> global.
// ---------------------------------------------------------------------------
__global__ __launch_bounds__(256)
void k1_kernel(const float4* __restrict__ x, const float* __restrict__ p,
               const float* __restrict__ U, const float* __restrict__ V)
{
    const int b = blockIdx.x, t = threadIdx.x;
    if (b < 4096) {
        if (b == 0) {
            g_sigma[t]       = sigmoid_sig(p[t]);
            g_sigma[t + 256] = sigmoid_sig(p[t + 256]);
        }
        const int i = b * 256 + t;
        float4 v = x[i];
        __half2* h = (__half2*)g_xh;
        h[i * 2 + 0] = __floats2half2_rn(v.x, v.y);
        h[i * 2 + 1] = __floats2half2_rn(v.z, v.w);
    } else if (b < 5120) {
        const int task = (b - 4096) * 8 + (t >> 5);
        const int lane = t & 31;
        const int mat = task >> 12;
        const int e = task & 4095;
        const int a = e >> 6, c = e & 63;
        const float* M = mat ? V : U;
        const float4* ra = (const float4*)(M + (size_t)a * 512);
        const float4* rb = (const float4*)(M + (size_t)c * 512);
        float ss = 0.f;
        #pragma unroll
        for (int j = lane; j < 128; j += 32)
            ss += dot4(__ldg(&ra[j]), __ldg(&rb[j]));
        #pragma unroll
        for (int o = 16; o > 0; o >>= 1) ss += __shfl_xor_sync(0xffffffffu, ss, o);
        if (lane == 0) g_gram[mat][a][c] = ss;
    } else {
        __shared__ float ssig[512];
        ssig[t]       = sigmoid_sig(p[t]);
        ssig[t + 256] = sigmoid_sig(p[t + 256]);
        __syncthreads();
        const int task = (b - 5120) * 8 + (t >> 5);
        const int lane = t & 31;
        const int k = task >> 6, bb = task & 63;
        const float4* ru = (const float4*)(U + (size_t)k * 512);
        const float4* rv = (const float4*)(V + (size_t)(63 - bb) * 512);
        const float4* sg = (const float4*)ssig;
        float ss = 0.f;
        #pragma unroll
        for (int j = lane; j < 128; j += 32) {
            float4 a4 = __ldg(&ru[j]), b4 = __ldg(&rv[j]), s4 = sg[j];
            ss += a4.x * s4.x * b4.x + a4.y * s4.y * b4.y
                + a4.z * s4.z * b4.z + a4.w * s4.w * b4.w;
        }
        #pragma unroll
        for (int o = 16; o > 0; o >>= 1) ss += __shfl_xor_sync(0xffffffffu, ss, o);
        if (lane == 0) g_XG[k * 64 + bb] = ss;
    }
}

// ---------------------------------------------------------------------------
// tinv (proven): T = inv(D^-1 + strict_upper(Gram)). 4 blocks.
// ---------------------------------------------------------------------------
__global__ __launch_bounds__(1024)
void tinv_kernel()
{
    __shared__ float Gs[2][64][64];
    const int t = threadIdx.x;
    for (int i = t; i < 2 * 4096; i += 1024)
        ((float*)Gs)[i] = ((const float*)g_gram)[i];
    __syncthreads();

    const int w = t >> 5, lane = t & 31;
    const int task = w + 32 * blockIdx.x;
    const int mat = task >> 6, c = task & 63;
    auto Lv = [&](int a, int m) -> float {
        if (mat == 0) return (a == m) ? Gs[0][a][a] * 0.5f : Gs[0][a][m];
        return (a == m) ? Gs[1][63 - a][63 - a] * 0.5f : Gs[1][63 - a][63 - m];
    };
    float t0 = 0.f, t1 = 0.f;
    {
        const float inv = 1.0f / Lv(c, c);
        if (lane == c) t0 = inv;
        if (lane + 32 == c) t1 = inv;
    }
    for (int a = c - 1; a >= 0; --a) {
        float s = 0.f;
        if (lane > a && lane <= c)            s += Lv(a, lane) * t0;
        if (lane + 32 > a && lane + 32 <= c)  s += Lv(a, lane + 32) * t1;
        #pragma unroll
        for (int o = 16; o > 0; o >>= 1) s += __shfl_xor_sync(0xffffffffu, s, o);
        const float ta = -s / Lv(a, a);
        if (lane == a) t0 = ta;
        if (lane + 32 == a) t1 = ta;
    }
    g_T[mat][lane][c]      = t0;
    g_T[mat][lane + 32][c] = t1;
}

// ---------------------------------------------------------------------------
// fusedM (R15-proven): block per 64x64 tile of M; all small mms local.
// ---------------------------------------------------------------------------
#define FM_SMEM ((7 * 4096 + 128) * 4)

__global__ __launch_bounds__(256)
void fusedM_kernel(const float* __restrict__ U, const float* __restrict__ V)
{
    extern __shared__ __align__(16) float dyn[];
    float* R0 = dyn;
    float* R1 = dyn + 4096;
    float* R2 = dyn + 8192;
    float* R3 = dyn + 12288;
    float* R4 = dyn + 16384;
    float* R5 = dyn + 20480;
    float* R6 = dyn + 24576;
    float* sgi = dyn + 28672;
    float* sgj = sgi + 64;

    const int t = threadIdx.x;
    const int ti = t & 15, tj = t >> 4;
    const int i0 = (blockIdx.x & 7) * 64, j0 = (blockIdx.x >> 3) * 64;

    for (int idx = t; idx < 4096; idx += 256)
        R0[(idx & 63) * 64 + (idx >> 6)] = (&g_T[0][0][0])[idx];
    for (int idx = t; idx < 1024; idx += 256)
        ((float4*)R1)[idx] = ((const float4*)g_XG)[idx];
    if (t < 64)        sgi[t] = g_sigma[i0 + t];
    else if (t < 128)  sgj[t - 64] = g_sigma[j0 + (t - 64)];
    __syncthreads();

    float acc[4][4];
    #define ZERO_ACC() { _Pragma("unroll") for (int r = 0; r < 4; ++r) \
                         _Pragma("unroll") for (int c = 0; c < 4; ++c) acc[r][c] = 0.f; }
    #define MM_STEP(Abuf, Bbuf, k) { \
        float4 av = *(const float4*)&(Abuf)[(k) * 64 + ti * 4]; \
        float4 bv = *(const float4*)&(Bbuf)[(k) * 64 + tj * 4]; \
        const float aa[4] = { av.x, av.y, av.z, av.w }; \
        const float bb[4] = { bv.x, bv.y, bv.z, bv.w }; \
        _Pragma("unroll") for (int r = 0; r < 4; ++r) \
        _Pragma("unroll") for (int c = 0; c < 4; ++c) acc[r][c] += aa[r] * bb[c]; }

    ZERO_ACC();
    #pragma unroll 4
    for (int k = 0; k < 64; ++k) MM_STEP(R0, R1, k);
    #pragma unroll
    for (int r = 0; r < 4; ++r)
        *(float4*)&R2[(ti * 4 + r) * 64 + tj * 4]
            = make_float4(acc[r][0], acc[r][1], acc[r][2], acc[r][3]);
    __syncthreads();

    for (int idx = t; idx < 1024; idx += 256) {
        const int row = idx >> 4, c4 = idx & 15;
        *(float4*)&R3[row * 64 + c4 * 4]
            = __ldg((const float4*)&U[(size_t)row * 512 + j0 + c4 * 4]);
    }
    __syncthreads();
    ZERO_ACC();
    #pragma unroll 4
    for (int k = 0; k < 64; ++k) MM_STEP(R0, R3, k);
    {
        const float s0 = sgj[tj * 4], s1 = sgj[tj * 4 + 1];
        const float s2 = sgj[tj * 4 + 2], s3 = sgj[tj * 4 + 3];
        #pragma unroll
        for (int r = 0; r < 4; ++r)
            *(float4*)&R4[(ti * 4 + r) * 64 + tj * 4]
                = make_float4(acc[r][0] * s0, acc[r][1] * s1, acc[r][2] * s2, acc[r][3] * s3);
    }
    __syncthreads();

    for (int idx = t; idx < 4096; idx += 256)
        R1[(idx & 63) * 64 + (idx >> 6)] = (&g_T[1][0][0])[idx];
    for (int idx = t; idx < 1024; idx += 256) {
        const int row = idx >> 4, c4 = idx & 15;
        *(float4*)&R3[row * 64 + c4 * 4]
            = __ldg((const float4*)&V[(size_t)(63 - row) * 512 + j0 + c4 * 4]);
    }
    __syncthreads();
    ZERO_ACC();
    #pragma unroll 4
    for (int k = 0; k < 64; ++k) MM_STEP(R1, R3, k);
    #pragma unroll
    for (int r = 0; r < 4; ++r)
        *(float4*)&R5[(ti * 4 + r) * 64 + tj * 4]
            = make_float4(acc[r][0], acc[r][1], acc[r][2], acc[r][3]);
    __syncthreads();

    for (int idx = t; idx < 1024; idx += 256) {
        const int row = idx >> 4, c4 = idx & 15;
        *(float4*)&R0[row * 64 + c4 * 4]
            = __ldg((const float4*)&U[(size_t)row * 512 + i0 + c4 * 4]);
        *(float4*)&R1[row * 64 + c4 * 4]
            = __ldg((const float4*)&V[(size_t)(63 - row) * 512 + i0 + c4 * 4]);
    }
    __syncthreads();

    ZERO_ACC();
    #pragma unroll 4
    for (int a = 0; a < 64; ++a) MM_STEP(R0, R2, a);
    {
        const float s0 = sgi[ti * 4], s1 = sgi[ti * 4 + 1];
        const float s2 = sgi[ti * 4 + 2], s3 = sgi[ti * 4 + 3];
        #pragma unroll
        for (int c = 0; c < 4; ++c) {
            const int b = tj * 4 + c;
            float4 vl = *(const float4*)&R1[b * 64 + ti * 4];
            *(float4*)&R6[b * 64 + ti * 4]
                = make_float4(s0 * vl.x - acc[0][c], s1 * vl.y - acc[1][c],
                              s2 * vl.z - acc[2][c], s3 * vl.w - acc[3][c]);
        }
    }
    __syncthreads();

    ZERO_ACC();
    #pragma unroll 4
    for (int a = 0; a < 64; ++a) MM_STEP(R0, R4, a);
    #pragma unroll 4
    for (int b = 0; b < 64; ++b) MM_STEP(R6, R5, b);
    #pragma unroll
    for (int c = 0; c < 4; ++c) {
        const int j = j0 + tj * 4 + c;
        float m[4];
        #pragma unroll
        for (int r = 0; r < 4; ++r) {
            const int i = i0 + ti * 4 + r;
            m[r] = -acc[r][c] + (i == j ? sgi[ti * 4 + r] : 0.f);
        }
        __half* dst = &g_MT[(size_t)j * 512 + i0 + ti * 4];
        *(__half2*)(dst)     = __floats2half2_rn(m[0], m[1]);
        *(__half2*)(dst + 2) = __floats2half2_rn(m[2], m[3]);
    }
}

// ---------------------------------------------------------------------------
// GEMM: out = x_h * M + bias. K=512, CTA 128x128, K-step 64, 3 stages,
// 128B-row SW128 layout. 96KB dynamic smem, occ 2.
// ---------------------------------------------------------------------------
#define TM 128
#define TN 128
#define NKS 8
#define STG 32768          // 16KB A + 16KB B per stage
#define GEMM_SMEM (3 * STG)

__global__ __launch_bounds__(256, 2)
void gemm_kernel(float* __restrict__ out, const float* __restrict__ bias)
{
    extern __shared__ __align__(1024) uint8_t smem[];
    const uint32_t sbase = smem_u32(smem);
    const int t = threadIdx.x;
    const int lane = t & 31, wid = t >> 5;
    const int wm = wid & 3, wn = wid >> 2;
    const int m0 = blockIdx.x * TM, n0 = blockIdx.y * TN;

    float acc[2][8][4];
    #pragma unroll
    for (int fm = 0; fm < 2; ++fm)
        #pragma unroll
        for (int fn = 0; fn < 8; ++fn)
            #pragma unroll
            for (int j = 0; j < 4; ++j) acc[fm][fn][j] = 0.f;

    // stage ks covers k in [ks*64, ks*64+64). Rows of 64 halves = 128 bytes.
    auto load_stage = [&](int st, int ks) {
        const __half* Ab = g_xh + (size_t)m0 * 512 + ks * 64;
        const __half* Bb = (const __half*)g_MT + (size_t)n0 * 512 + ks * 64;
        const uint32_t sA = sbase + st * STG;
        const uint32_t sB = sA + 16384;
        #pragma unroll
        for (int i = 0; i < 4; ++i) {
            const int idx = t + i * 256;          // 0..1023
            const int row = idx >> 3, c = idx & 7;
            cp_async16(sA + SWZ128((uint32_t)(row * 128 + c * 16)),
                       Ab + (size_t)row * 512 + c * 8);
        }
        #pragma unroll
        for (int i = 0; i < 4; ++i) {
            const int idx = t + i * 256;
            const int row = idx >> 3, c = idx & 7;
            cp_async16(sB + SWZ128((uint32_t)(row * 128 + c * 16)),
                       Bb + (size_t)row * 512 + c * 8);
        }
    };

    auto compute_stage = [&](int st) {
        const uint32_t sA = sbase + st * STG;
        const uint32_t sB = sA + 16384;
        #pragma unroll
        for (int kf = 0; kf < 4; ++kf) {
            uint32_t a[2][4], b[4][4];
            #pragma unroll
            for (int fm = 0; fm < 2; ++fm) {
                const int row = wm * 32 + fm * 16 + (lane & 15);
                const int c   = kf * 2 + (lane >> 4);
                ldsm_x4(a[fm], sA + SWZ128((uint32_t)(row * 128 + c * 16)));
            }
            #pragma unroll
            for (int fp = 0; fp < 4; ++fp) {
                const int row = wn * 64 + fp * 16 + ((lane >> 4) << 3) + (lane & 7);
                const int c   = kf * 2 + ((lane >> 3) & 1);
                ldsm_x4(b[fp], sB + SWZ128((uint32_t)(row * 128 + c * 16)));
            }
            #pragma unroll
            for (int fm = 0; fm < 2; ++fm)
                #pragma unroll
                for (int fn = 0; fn < 8; ++fn)
                    mma16816(acc[fm][fn], a[fm], &b[fn >> 1][(fn & 1) * 2]);
        }
    };

    load_stage(0, 0); CP_COMMIT();
    load_stage(1, 1); CP_COMMIT();

    #pragma unroll 1
    for (int ks = 0; ks < NKS; ++ks) {
        CP_WAIT1();
        __syncthreads();
        const int kn = ks + 2;
        if (kn < NKS) load_stage(kn % 3, kn);
        CP_COMMIT();
        compute_stage(ks % 3);
    }

    #pragma unroll
    for (int fm = 0; fm < 2; ++fm) {
        const int r = m0 + wm * 32 + fm * 16 + (lane >> 2);
        #pragma unroll
        for (int fn = 0; fn < 8; ++fn) {
            const int cb = n0 + wn * 64 + fn * 8 + (lane & 3) * 2;
            const float2 bi = __ldg((const float2*)(bias + cb));
            float2 v0, v1;
            v0.x = acc[fm][fn][0] + bi.x; v0.y = acc[fm][fn][1] + bi.y;
            v1.x = acc[fm][fn][2] + bi.x; v1.y = acc[fm][fn][3] + bi.y;
            *(float2*)(out + (size_t)r * 512 + cb)       = v0;
            *(float2*)(out + (size_t)(r + 8) * 512 + cb) = v1;
        }
    }
}

// ---------------------------------------------------------------------------
extern "C" void kernel_launch(void* const* d_in, const int* in_sizes, int n_in,
                              void* d_out, int out_size)
{
    (void)in_sizes; (void)n_in; (void)out_size;
    const float* x    = (const float*)d_in[0];
    const float* p    = (const float*)d_in[1];
    const float* U    = (const float*)d_in[2];
    const float* V    = (const float*)d_in[3];
    const float* bias = (const float*)d_in[4];

    cudaFuncSetAttribute(fusedM_kernel, cudaFuncAttributeMaxDynamicSharedMemorySize,
                         FM_SMEM);
    cudaFuncSetAttribute(gemm_kernel, cudaFuncAttributeMaxDynamicSharedMemorySize,
                         GEMM_SMEM);

    k1_kernel<<<4096 + 1024 + 512, 256>>>((const float4*)x, p, U, V);
    tinv_kernel<<<4, 1024>>>();
    fusedM_kernel<<<64, 256, FM_SMEM>>>(U, V);
    gemm_kernel<<<dim3(BATCH / TM, 512 / TN), 256, GEMM_SMEM>>>((float*)d_out, bias);
}